// round 7
// baseline (speedup 1.0000x reference)
#include <cuda_runtime.h>
#include <math.h>

// Problem constants
#define NB   2
#define NS   2048
#define NH   16
#define ND   64
#define NHID 1024
#define NCK  64      // chunk size
#define NNC  32      // chunks per sequence
#define NBH  32      // NB*NH
#define PST  68      // padded smem row stride (floats); 68*4B = 17*16B (keeps float4 alignment)

typedef unsigned long long u64;

// Scratch (static device globals -- no allocation allowed)
__device__ float4 g_tab[NS * 32];              // xPos table: (cos*sc, sin*sc, cos/sc, sin/sc)
__device__ float  g_A [NBH * NNC * ND * ND];   // per-chunk state contributions
__device__ float  g_St[NBH * NNC * ND * ND];   // prefix-scanned states (state BEFORE chunk c)

__device__ __forceinline__ double head_lg(int h) {
    const double L0 = -3.4657359027997265;   // log(1/32)
    const double L1 = -6.2383246250395075;   // log(1/512)
    double g = 1.0 - exp(L0 + (L1 - L0) * ((double)h / 15.0));
    return log(g);
}

// ---- packed f32x2 helpers (Blackwell-only fma.rn.f32x2: 2 FMA per issue) ----
__device__ __forceinline__ u64 pk2(float x) {
    unsigned xi = __float_as_uint(x);
    u64 r; asm("mov.b64 %0, {%1, %1};" : "=l"(r) : "r"(xi)); return r;
}
__device__ __forceinline__ u64 ffma2(u64 a, u64 b, u64 c) {
    u64 d; asm("fma.rn.f32x2 %0, %1, %2, %3;" : "=l"(d) : "l"(a), "l"(b), "l"(c)); return d;
}
__device__ __forceinline__ float2 up2(u64 v) {
    unsigned lo, hi; asm("mov.b64 {%0, %1}, %2;" : "=r"(lo), "=r"(hi) : "l"(v));
    return make_float2(__uint_as_float(lo), __uint_as_float(hi));
}

// ---------------------------------------------------------------------------
// Kernel 0: xPos table. tab[s][i] = (cos*sc, sin*sc, cos/sc, sin/sc)
// 65536 threads total -- transcendentals computed ONCE, not per (b,h,s).
// ---------------------------------------------------------------------------
__global__ __launch_bounds__(256)
void table_kernel() {
    int idx = blockIdx.x * 256 + threadIdx.x;   // [0, 2048*32)
    int i = idx & 31;
    int s = idx >> 5;
    float invf = (float)(1.0 / pow(10000.0, (double)i / 32.0));
    float bs   = (2.0f * (float)i + 25.6f) / 89.6f;   // (2i + 0.4*64)/(1.4*64)
    float pos  = (float)s;
    float sn, cs;
    sincosf(pos * invf, &sn, &cs);
    float sc = powf(bs, pos * (1.0f / 512.0f));
    float iv = 1.0f / sc;
    g_tab[idx] = make_float4(cs * sc, sn * sc, cs * iv, sn * iv);
}

// ---------------------------------------------------------------------------
// Kernel 1: per-chunk state contribution A_c[d][e] = sum_j gamma^(C-j) k'[j][d] v[j][e]
// Rotation fused into staging. 128 threads, 4d x 8e micro-tile, f32x2 FMAs.
// ---------------------------------------------------------------------------
__global__ __launch_bounds__(128)
void passA_kernel(const float* __restrict__ K, const float* __restrict__ V) {
    __shared__ float ks[NCK * PST];   // [j][d] rotated+weighted K
    __shared__ float vs[NCK * PST];   // [j][e]

    int c = blockIdx.x, h = blockIdx.y, b = blockIdx.z;
    int bh = b * NH + h;
    int tid = threadIdx.x;
    int c0 = c * NCK;
    float lgf = (float)head_lg(h);

    // staging: 2 threads per row s, each covers 32 floats
    {
        int s = tid >> 1, half = tid & 1;
        float w = expf(lgf * (float)(NCK - s));   // gamma^(C-j)
        size_t ro = ((size_t)(b * NS + c0 + s)) * NHID + h * ND;
        const float* krow = K + ro;
        const float* vrow = V + ro;
        const float4* tb = g_tab + (size_t)(c0 + s) * 32;
#pragma unroll
        for (int p = 0; p < 8; ++p) {
            int d0 = 32 * half + 4 * p;
            float4 kv = *(const float4*)(krow + d0);
            float4 t0 = tb[d0 >> 1], t1 = tb[(d0 >> 1) + 1];
            float4 kr;
            kr.x = (kv.x * t0.z - kv.y * t0.w) * w;
            kr.y = (kv.y * t0.z + kv.x * t0.w) * w;
            kr.z = (kv.z * t1.z - kv.w * t1.w) * w;
            kr.w = (kv.w * t1.z + kv.z * t1.w) * w;
            *(float4*)(ks + s * PST + d0) = kr;
            *(float4*)(vs + s * PST + d0) = *(const float4*)(vrow + d0);
        }
    }
    __syncthreads();

    int tx = tid & 7, ty = tid >> 3;
    int d0g = 4 * ty, e0 = 8 * tx;
    u64 acc[4][4];
#pragma unroll
    for (int r = 0; r < 4; ++r)
#pragma unroll
        for (int e = 0; e < 4; ++e) acc[r][e] = 0ull;

#pragma unroll 8
    for (int j = 0; j < NCK; ++j) {
        float4 av = *(const float4*)(ks + j * PST + d0g);
        u64 a0 = pk2(av.x), a1 = pk2(av.y), a2 = pk2(av.z), a3 = pk2(av.w);
        ulonglong2 bA = *(const ulonglong2*)(vs + j * PST + e0);
        ulonglong2 bB = *(const ulonglong2*)(vs + j * PST + e0 + 4);
        acc[0][0] = ffma2(a0, bA.x, acc[0][0]); acc[0][1] = ffma2(a0, bA.y, acc[0][1]);
        acc[0][2] = ffma2(a0, bB.x, acc[0][2]); acc[0][3] = ffma2(a0, bB.y, acc[0][3]);
        acc[1][0] = ffma2(a1, bA.x, acc[1][0]); acc[1][1] = ffma2(a1, bA.y, acc[1][1]);
        acc[1][2] = ffma2(a1, bB.x, acc[1][2]); acc[1][3] = ffma2(a1, bB.y, acc[1][3]);
        acc[2][0] = ffma2(a2, bA.x, acc[2][0]); acc[2][1] = ffma2(a2, bA.y, acc[2][1]);
        acc[2][2] = ffma2(a2, bB.x, acc[2][2]); acc[2][3] = ffma2(a2, bB.y, acc[2][3]);
        acc[3][0] = ffma2(a3, bA.x, acc[3][0]); acc[3][1] = ffma2(a3, bA.y, acc[3][1]);
        acc[3][2] = ffma2(a3, bB.x, acc[3][2]); acc[3][3] = ffma2(a3, bB.y, acc[3][3]);
    }

    float* ag = g_A + ((size_t)bh * NNC + c) * ND * ND;
#pragma unroll
    for (int r = 0; r < 4; ++r) {
        float2 p0 = up2(acc[r][0]), p1 = up2(acc[r][1]), p2 = up2(acc[r][2]), p3 = up2(acc[r][3]);
        *(float4*)(ag + (d0g + r) * ND + e0)     = make_float4(p0.x, p0.y, p1.x, p1.y);
        *(float4*)(ag + (d0g + r) * ND + e0 + 4) = make_float4(p2.x, p2.y, p3.x, p3.y);
    }
}

// ---------------------------------------------------------------------------
// Kernel 2: sequential prefix scan over chunks: St_{c+1} = gamma^C * St_c + A_c
// ---------------------------------------------------------------------------
__global__ __launch_bounds__(256)
void scan_kernel() {
    int bh = blockIdx.x;
    int h = bh & (NH - 1);
    int tid = threadIdx.x;
    double lg = head_lg(h);
    float dec = (float)exp(lg * (double)NCK);

    float st[16];
#pragma unroll
    for (int k = 0; k < 16; ++k) st[k] = 0.0f;

    size_t base = (size_t)bh * NNC * ND * ND;
    for (int c = 0; c < NNC; ++c) {
        size_t off = base + (size_t)c * ND * ND + tid;
#pragma unroll
        for (int k = 0; k < 16; ++k) {
            g_St[off + k * 256] = st[k];
            st[k] = st[k] * dec + g_A[off + k * 256];
        }
    }
}

// ---------------------------------------------------------------------------
// Kernel 3: per-chunk output (rotation fused into staging).
//   q' = gamma^i rot_up(q),  k' = gamma^{-j} rot_dn(k)
//   P[i][j] = (q'_i . k'_j) masked j<=i     O = P.V + Q'.St
// 128 threads, 4i x 8e micro-tile, f32x2; GEMM1 fused with Q'.St (shared a-loads).
// smem: qsT | ksT(->psT) | vs | sts  = 4 * 64*68*4B = 68 KB -> 3 CTAs/SM
// ---------------------------------------------------------------------------
extern __shared__ float smC[];

__global__ __launch_bounds__(128)
void passC_kernel(const float* __restrict__ Q, const float* __restrict__ K,
                  const float* __restrict__ V, float* __restrict__ out) {
    float* qsT = smC;                   // [d][i] transposed rotated Q'
    float* ksT = smC + NCK * PST;       // [d][j] transposed rotated K'; reused as psT [j][i]
    float* vs  = smC + 2 * NCK * PST;   // [j][e]
    float* sts = smC + 3 * NCK * PST;   // [d'][e]

    int c = blockIdx.x, h = blockIdx.y, b = blockIdx.z;
    int bh = b * NH + h;
    int tid = threadIdx.x;
    int c0 = c * NCK;
    float lgf = (float)head_lg(h);

    // ---- staging with fused rotation ----
    {
        int s = tid >> 1, half = tid & 1;
        float wq = expf(lgf * (float)s);     // gamma^i
        float wk = expf(-lgf * (float)s);    // gamma^{-j}
        size_t ro = ((size_t)(b * NS + c0 + s)) * NHID + h * ND;
        const float* qrow = Q + ro;
        const float* krow = K + ro;
        const float* vrow = V + ro;
        const float* strow = g_St + ((size_t)bh * NNC + c) * ND * ND + s * ND;
        const float4* tb = g_tab + (size_t)(c0 + s) * 32;
#pragma unroll
        for (int p = 0; p < 8; ++p) {
            int d0 = 32 * half + 4 * p;
            float4 qv = *(const float4*)(qrow + d0);
            float4 kv = *(const float4*)(krow + d0);
            float4 t0 = tb[d0 >> 1], t1 = tb[(d0 >> 1) + 1];
            qsT[(d0 + 0) * PST + s] = (qv.x * t0.x - qv.y * t0.y) * wq;
            qsT[(d0 + 1) * PST + s] = (qv.y * t0.x + qv.x * t0.y) * wq;
            qsT[(d0 + 2) * PST + s] = (qv.z * t1.x - qv.w * t1.y) * wq;
            qsT[(d0 + 3) * PST + s] = (qv.w * t1.x + qv.z * t1.y) * wq;
            ksT[(d0 + 0) * PST + s] = (kv.x * t0.z - kv.y * t0.w) * wk;
            ksT[(d0 + 1) * PST + s] = (kv.y * t0.z + kv.x * t0.w) * wk;
            ksT[(d0 + 2) * PST + s] = (kv.z * t1.z - kv.w * t1.w) * wk;
            ksT[(d0 + 3) * PST + s] = (kv.w * t1.z + kv.z * t1.w) * wk;
            *(float4*)(vs  + s * PST + d0) = *(const float4*)(vrow + d0);
            *(float4*)(sts + s * PST + d0) = *(const float4*)(strow + d0);
        }
    }
    __syncthreads();

    int tx = tid & 7, ty = tid >> 3;
    int i0 = 4 * ty, e0 = 8 * tx;      // e0 doubles as j0 for P

    u64 accP[4][4], accO[4][4];
#pragma unroll
    for (int r = 0; r < 4; ++r)
#pragma unroll
        for (int e = 0; e < 4; ++e) { accP[r][e] = 0ull; accO[r][e] = 0ull; }

    // ---- fused d-loop: P = Q'.K'^T  and  O += Q'.St  (shared a-loads) ----
#pragma unroll 8
    for (int d = 0; d < ND; ++d) {
        float4 av = *(const float4*)(qsT + d * PST + i0);
        u64 a0 = pk2(av.x), a1 = pk2(av.y), a2 = pk2(av.z), a3 = pk2(av.w);
        ulonglong2 kA = *(const ulonglong2*)(ksT + d * PST + e0);
        ulonglong2 kB = *(const ulonglong2*)(ksT + d * PST + e0 + 4);
        ulonglong2 sA = *(const ulonglong2*)(sts + d * PST + e0);
        ulonglong2 sB = *(const ulonglong2*)(sts + d * PST + e0 + 4);
        accP[0][0] = ffma2(a0, kA.x, accP[0][0]); accP[0][1] = ffma2(a0, kA.y, accP[0][1]);
        accP[0][2] = ffma2(a0, kB.x, accP[0][2]); accP[0][3] = ffma2(a0, kB.y, accP[0][3]);
        accP[1][0] = ffma2(a1, kA.x, accP[1][0]); accP[1][1] = ffma2(a1, kA.y, accP[1][1]);
        accP[1][2] = ffma2(a1, kB.x, accP[1][2]); accP[1][3] = ffma2(a1, kB.y, accP[1][3]);
        accP[2][0] = ffma2(a2, kA.x, accP[2][0]); accP[2][1] = ffma2(a2, kA.y, accP[2][1]);
        accP[2][2] = ffma2(a2, kB.x, accP[2][2]); accP[2][3] = ffma2(a2, kB.y, accP[2][3]);
        accP[3][0] = ffma2(a3, kA.x, accP[3][0]); accP[3][1] = ffma2(a3, kA.y, accP[3][1]);
        accP[3][2] = ffma2(a3, kB.x, accP[3][2]); accP[3][3] = ffma2(a3, kB.y, accP[3][3]);
        accO[0][0] = ffma2(a0, sA.x, accO[0][0]); accO[0][1] = ffma2(a0, sA.y, accO[0][1]);
        accO[0][2] = ffma2(a0, sB.x, accO[0][2]); accO[0][3] = ffma2(a0, sB.y, accO[0][3]);
        accO[1][0] = ffma2(a1, sA.x, accO[1][0]); accO[1][1] = ffma2(a1, sA.y, accO[1][1]);
        accO[1][2] = ffma2(a1, sB.x, accO[1][2]); accO[1][3] = ffma2(a1, sB.y, accO[1][3]);
        accO[2][0] = ffma2(a2, sA.x, accO[2][0]); accO[2][1] = ffma2(a2, sA.y, accO[2][1]);
        accO[2][2] = ffma2(a2, sB.x, accO[2][2]); accO[2][3] = ffma2(a2, sB.y, accO[2][3]);
        accO[3][0] = ffma2(a3, sA.x, accO[3][0]); accO[3][1] = ffma2(a3, sA.y, accO[3][1]);
        accO[3][2] = ffma2(a3, sB.x, accO[3][2]); accO[3][3] = ffma2(a3, sB.y, accO[3][3]);
    }
    __syncthreads();   // everyone done reading ksT

    // ---- mask + write P transposed into ksT's space: psT[j][i] ----
    float* psT = ksT;
#pragma unroll
    for (int e = 0; e < 4; ++e) {
        float2 v0 = up2(accP[0][e]), v1 = up2(accP[1][e]), v2 = up2(accP[2][e]), v3 = up2(accP[3][e]);
        int ja = e0 + 2 * e, jb = ja + 1;
        float4 wa, wb;
        wa.x = (ja <= i0 + 0) ? v0.x : 0.0f; wa.y = (ja <= i0 + 1) ? v1.x : 0.0f;
        wa.z = (ja <= i0 + 2) ? v2.x : 0.0f; wa.w = (ja <= i0 + 3) ? v3.x : 0.0f;
        wb.x = (jb <= i0 + 0) ? v0.y : 0.0f; wb.y = (jb <= i0 + 1) ? v1.y : 0.0f;
        wb.z = (jb <= i0 + 2) ? v2.y : 0.0f; wb.w = (jb <= i0 + 3) ? v3.y : 0.0f;
        *(float4*)(psT + ja * PST + i0) = wa;
        *(float4*)(psT + jb * PST + i0) = wb;
    }
    __syncthreads();

    // ---- O += P.V ----
#pragma unroll 8
    for (int j = 0; j < NCK; ++j) {
        float4 av = *(const float4*)(psT + j * PST + i0);
        u64 a0 = pk2(av.x), a1 = pk2(av.y), a2 = pk2(av.z), a3 = pk2(av.w);
        ulonglong2 bA = *(const ulonglong2*)(vs + j * PST + e0);
        ulonglong2 bB = *(const ulonglong2*)(vs + j * PST + e0 + 4);
        accO[0][0] = ffma2(a0, bA.x, accO[0][0]); accO[0][1] = ffma2(a0, bA.y, accO[0][1]);
        accO[0][2] = ffma2(a0, bB.x, accO[0][2]); accO[0][3] = ffma2(a0, bB.y, accO[0][3]);
        accO[1][0] = ffma2(a1, bA.x, accO[1][0]); accO[1][1] = ffma2(a1, bA.y, accO[1][1]);
        accO[1][2] = ffma2(a1, bB.x, accO[1][2]); accO[1][3] = ffma2(a1, bB.y, accO[1][3]);
        accO[2][0] = ffma2(a2, bA.x, accO[2][0]); accO[2][1] = ffma2(a2, bA.y, accO[2][1]);
        accO[2][2] = ffma2(a2, bB.x, accO[2][2]); accO[2][3] = ffma2(a2, bB.y, accO[2][3]);
        accO[3][0] = ffma2(a3, bA.x, accO[3][0]); accO[3][1] = ffma2(a3, bA.y, accO[3][1]);
        accO[3][2] = ffma2(a3, bB.x, accO[3][2]); accO[3][3] = ffma2(a3, bB.y, accO[3][3]);
    }

    float* og = out + ((size_t)(b * NS + c0)) * NHID + h * ND;
#pragma unroll
    for (int r = 0; r < 4; ++r) {
        float2 p0 = up2(accO[r][0]), p1 = up2(accO[r][1]), p2 = up2(accO[r][2]), p3 = up2(accO[r][3]);
        *(float4*)(og + (size_t)(i0 + r) * NHID + e0)     = make_float4(p0.x, p0.y, p1.x, p1.y);
        *(float4*)(og + (size_t)(i0 + r) * NHID + e0 + 4) = make_float4(p2.x, p2.y, p3.x, p3.y);
    }
}

// ---------------------------------------------------------------------------
extern "C" void kernel_launch(void* const* d_in, const int* in_sizes, int n_in,
                              void* d_out, int out_size) {
    (void)in_sizes; (void)n_in; (void)out_size;
    const float* Q = (const float*)d_in[0];
    const float* K = (const float*)d_in[1];
    const float* V = (const float*)d_in[2];
    float* out = (float*)d_out;

    table_kernel<<<(NS * 32) / 256, 256>>>();

    dim3 grid(NNC, NH, NB);
    passA_kernel<<<grid, 128>>>(K, V);
    scan_kernel<<<NBH, 256>>>();

    size_t shm = (size_t)4 * NCK * PST * sizeof(float);   // 69632 B
    cudaFuncSetAttribute(passC_kernel, cudaFuncAttributeMaxDynamicSharedMemorySize, (int)shm);
    passC_kernel<<<grid, 128, shm>>>(Q, K, V, out);
}

// round 8
// speedup vs baseline: 1.3205x; 1.3205x over previous
#include <cuda_runtime.h>
#include <math.h>

// Problem constants
#define NB   2
#define NS   2048
#define NH   16
#define ND   64
#define NHID 1024
#define NCK  64      // chunk size
#define NNC  32      // chunks per sequence
#define NBH  32      // NB*NH
#define PST  68      // padded smem row stride (floats)

// Scratch (static device globals -- no allocation allowed)
__device__ float4 g_tab[NS * 32];              // xPos table: (cos*sc, sin*sc, cos/sc, sin/sc)
__device__ float  g_A [NBH * NNC * ND * ND];   // per-chunk state contributions
__device__ float  g_St[NBH * NNC * ND * ND];   // prefix-scanned states (state BEFORE chunk c)

__device__ __forceinline__ double head_lg(int h) {
    const double L0 = -3.4657359027997265;   // log(1/32)
    const double L1 = -6.2383246250395075;   // log(1/512)
    double g = 1.0 - exp(L0 + (L1 - L0) * ((double)h / 15.0));
    return log(g);
}

// ---------------------------------------------------------------------------
// Kernel 0: xPos table. tab[s][i] = (cos*sc, sin*sc, cos/sc, sin/sc)
// 65536 threads total -- transcendentals computed ONCE, not per (b,h,s).
// ---------------------------------------------------------------------------
__global__ __launch_bounds__(256)
void table_kernel() {
    int idx = blockIdx.x * 256 + threadIdx.x;   // [0, 2048*32)
    int i = idx & 31;
    int s = idx >> 5;
    float invf = (float)(1.0 / pow(10000.0, (double)i / 32.0));
    float bs   = (2.0f * (float)i + 25.6f) / 89.6f;   // (2i + 0.4*64)/(1.4*64)
    float pos  = (float)s;
    float sn, cs;
    sincosf(pos * invf, &sn, &cs);
    float sc = powf(bs, pos * (1.0f / 512.0f));
    float iv = 1.0f / sc;
    g_tab[idx] = make_float4(cs * sc, sn * sc, cs * iv, sn * iv);
}

// ---------------------------------------------------------------------------
// Kernel 1: per-chunk state contribution A_c[d][e] = sum_j gamma^(C-j) k'[j][d] v[j][e]
// Rotation fused into staging. 256 threads, 16x16 grid, 4x4 micro-tile (Round-6 GEMM).
// ---------------------------------------------------------------------------
__global__ __launch_bounds__(256)
void passA_kernel(const float* __restrict__ K, const float* __restrict__ V) {
    __shared__ float ks[NCK * PST];   // [j][d] rotated+weighted K
    __shared__ float vs[NCK * PST];   // [j][e]

    int c = blockIdx.x, h = blockIdx.y, b = blockIdx.z;
    int bh = b * NH + h;
    int tid = threadIdx.x;
    int c0 = c * NCK;
    float lgf = (float)head_lg(h);

    // staging with fused downscale-rotation: 4 threads per row, 16 floats each
    {
        int s = tid >> 2, qq = tid & 3;
        float w = expf(lgf * (float)(NCK - s));   // gamma^(C-j)
        size_t ro = ((size_t)(b * NS + c0 + s)) * NHID + h * ND;
        const float* krow = K + ro;
        const float* vrow = V + ro;
        const float4* tb = g_tab + (size_t)(c0 + s) * 32;
#pragma unroll
        for (int p = 0; p < 4; ++p) {
            int d0 = 16 * qq + 4 * p;
            float4 kv = *(const float4*)(krow + d0);
            float4 t0 = tb[d0 >> 1], t1 = tb[(d0 >> 1) + 1];
            float4 kr;
            kr.x = (kv.x * t0.z - kv.y * t0.w) * w;
            kr.y = (kv.y * t0.z + kv.x * t0.w) * w;
            kr.z = (kv.z * t1.z - kv.w * t1.w) * w;
            kr.w = (kv.w * t1.z + kv.z * t1.w) * w;
            *(float4*)(ks + s * PST + d0) = kr;
            *(float4*)(vs + s * PST + d0) = *(const float4*)(vrow + d0);
        }
    }
    __syncthreads();

    int ty = tid >> 4, tx = tid & 15;
    float acc[4][4];
#pragma unroll
    for (int di = 0; di < 4; ++di)
#pragma unroll
        for (int ei = 0; ei < 4; ++ei) acc[di][ei] = 0.0f;

#pragma unroll 8
    for (int j = 0; j < NCK; ++j) {
        float a0 = ks[j * PST + 4 * ty + 0];
        float a1 = ks[j * PST + 4 * ty + 1];
        float a2 = ks[j * PST + 4 * ty + 2];
        float a3 = ks[j * PST + 4 * ty + 3];
        float4 bv = *(const float4*)(vs + j * PST + 4 * tx);
        acc[0][0] += a0 * bv.x; acc[0][1] += a0 * bv.y; acc[0][2] += a0 * bv.z; acc[0][3] += a0 * bv.w;
        acc[1][0] += a1 * bv.x; acc[1][1] += a1 * bv.y; acc[1][2] += a1 * bv.z; acc[1][3] += a1 * bv.w;
        acc[2][0] += a2 * bv.x; acc[2][1] += a2 * bv.y; acc[2][2] += a2 * bv.z; acc[2][3] += a2 * bv.w;
        acc[3][0] += a3 * bv.x; acc[3][1] += a3 * bv.y; acc[3][2] += a3 * bv.z; acc[3][3] += a3 * bv.w;
    }

    float* ag = g_A + ((size_t)bh * NNC + c) * ND * ND;
#pragma unroll
    for (int di = 0; di < 4; ++di) {
        float4 w = make_float4(acc[di][0], acc[di][1], acc[di][2], acc[di][3]);
        *(float4*)&ag[(4 * ty + di) * ND + 4 * tx] = w;
    }
}

// ---------------------------------------------------------------------------
// Kernel 2: sequential prefix scan over chunks: St_{c+1} = gamma^C * St_c + A_c
// ---------------------------------------------------------------------------
__global__ __launch_bounds__(256)
void scan_kernel() {
    int bh = blockIdx.x;
    int h = bh & (NH - 1);
    int tid = threadIdx.x;
    double lg = head_lg(h);
    float dec = (float)exp(lg * (double)NCK);

    float st[16];
#pragma unroll
    for (int k = 0; k < 16; ++k) st[k] = 0.0f;

    size_t base = (size_t)bh * NNC * ND * ND;
    for (int c = 0; c < NNC; ++c) {
        size_t off = base + (size_t)c * ND * ND + tid;
#pragma unroll
        for (int k = 0; k < 16; ++k) {
            g_St[off + k * 256] = st[k];
            st[k] = st[k] * dec + g_A[off + k * 256];
        }
    }
}

// ---------------------------------------------------------------------------
// Kernel 3: per-chunk output. Rotation fused into staging, Round-6 GEMM bodies,
// ps overlaid on ksT (smem 85.5KB -> 68.6KB -> 3 CTAs/SM).
//   q' = gamma^i rot_up(q),  k' = gamma^{-j} rot_dn(k)
//   P[i][j] = (q'_i . k'_j) masked j<=i;   O = P.V + Q'.St
// ---------------------------------------------------------------------------
extern __shared__ float smC[];

__global__ __launch_bounds__(256)
void passC_kernel(const float* __restrict__ Q, const float* __restrict__ K,
                  const float* __restrict__ V, float* __restrict__ out) {
    float* qs  = smC;                            // [i][d]  NCK*PST
    float* ksT = smC + NCK * PST;                // [d][j] xor-swizzled, 4096 fl; reused as ps[i][j]
    float* vs  = smC + NCK * PST + NCK * NCK;    // [j][e]  NCK*PST
    float* sts = vs + NCK * PST;                 // [d'][e] NCK*PST

    int c = blockIdx.x, h = blockIdx.y, b = blockIdx.z;
    int bh = b * NH + h;
    int tid = threadIdx.x;
    int c0 = c * NCK;
    float lgf = (float)head_lg(h);

    // ---- staging with fused rotation: 4 threads per row, 16 floats each ----
    {
        int s = tid >> 2, qq = tid & 3;
        float wq = expf(lgf * (float)s);     // gamma^i
        float wk = expf(-lgf * (float)s);    // gamma^{-j}
        size_t ro = ((size_t)(b * NS + c0 + s)) * NHID + h * ND;
        const float* qrow = Q + ro;
        const float* krow = K + ro;
        const float* vrow = V + ro;
        const float4* tb = g_tab + (size_t)(c0 + s) * 32;
#pragma unroll
        for (int p = 0; p < 4; ++p) {
            int d0 = 16 * qq + 4 * p;
            float4 qv = *(const float4*)(qrow + d0);
            float4 kv = *(const float4*)(krow + d0);
            float4 t0 = tb[d0 >> 1], t1 = tb[(d0 >> 1) + 1];
            float4 qr;
            qr.x = (qv.x * t0.x - qv.y * t0.y) * wq;
            qr.y = (qv.y * t0.x + qv.x * t0.y) * wq;
            qr.z = (qv.z * t1.x - qv.w * t1.y) * wq;
            qr.w = (qv.w * t1.x + qv.z * t1.y) * wq;
            *(float4*)(qs + s * PST + d0) = qr;
            // transpose + xor swizzle for K'
            float k0 = (kv.x * t0.z - kv.y * t0.w) * wk;
            float k1 = (kv.y * t0.z + kv.x * t0.w) * wk;
            float k2 = (kv.z * t1.z - kv.w * t1.w) * wk;
            float k3 = (kv.w * t1.z + kv.z * t1.w) * wk;
            int sb = ((s >> 2) << 2);  // s rounded to 4
            ksT[(d0 + 0) * NCK + (((s >> 2) ^ ((d0 + 0) & 15)) << 2) + (s & 3)] = k0;
            ksT[(d0 + 1) * NCK + (((s >> 2) ^ ((d0 + 1) & 15)) << 2) + (s & 3)] = k1;
            ksT[(d0 + 2) * NCK + (((s >> 2) ^ ((d0 + 2) & 15)) << 2) + (s & 3)] = k2;
            ksT[(d0 + 3) * NCK + (((s >> 2) ^ ((d0 + 3) & 15)) << 2) + (s & 3)] = k3;
            (void)sb;
            *(float4*)(vs + s * PST + d0) = *(const float4*)(vrow + d0);
        }
    }
    // stage St (64x64) : 16 elems per thread
    {
        const float* stg = g_St + ((size_t)bh * NNC + c) * ND * ND;
#pragma unroll
        for (int t = 0; t < 16; ++t) {
            int idx = tid + t * 256;
            int r = idx >> 6, e = idx & 63;
            sts[r * PST + e] = stg[idx];
        }
    }
    __syncthreads();

    int ty = tid >> 4, tx = tid & 15;
    int i0 = 4 * ty, j0 = 4 * tx;

    // ---- GEMM1: P = Q'.K'^T ----
    float acc[4][4];
#pragma unroll
    for (int di = 0; di < 4; ++di)
#pragma unroll
        for (int ei = 0; ei < 4; ++ei) acc[di][ei] = 0.0f;

#pragma unroll 8
    for (int d = 0; d < ND; ++d) {
        float a0 = qs[(i0 + 0) * PST + d];
        float a1 = qs[(i0 + 1) * PST + d];
        float a2 = qs[(i0 + 2) * PST + d];
        float a3 = qs[(i0 + 3) * PST + d];
        float4 bv = *(const float4*)&ksT[d * NCK + ((tx ^ (d & 15)) << 2)];
        acc[0][0] += a0 * bv.x; acc[0][1] += a0 * bv.y; acc[0][2] += a0 * bv.z; acc[0][3] += a0 * bv.w;
        acc[1][0] += a1 * bv.x; acc[1][1] += a1 * bv.y; acc[1][2] += a1 * bv.z; acc[1][3] += a1 * bv.w;
        acc[2][0] += a2 * bv.x; acc[2][1] += a2 * bv.y; acc[2][2] += a2 * bv.z; acc[2][3] += a2 * bv.w;
        acc[3][0] += a3 * bv.x; acc[3][1] += a3 * bv.y; acc[3][2] += a3 * bv.z; acc[3][3] += a3 * bv.w;
    }
    __syncthreads();   // everyone done reading ksT before overwrite

    // ---- mask + stage P into ksT's space (row-major [i][j], stride NCK) ----
    float* ps = ksT;
#pragma unroll
    for (int di = 0; di < 4; ++di) {
        int ii = i0 + di;
        float4 w;
        w.x = (j0 + 0 <= ii) ? acc[di][0] : 0.0f;
        w.y = (j0 + 1 <= ii) ? acc[di][1] : 0.0f;
        w.z = (j0 + 2 <= ii) ? acc[di][2] : 0.0f;
        w.w = (j0 + 3 <= ii) ? acc[di][3] : 0.0f;
        *(float4*)&ps[ii * NCK + j0] = w;
    }
    __syncthreads();

    // ---- GEMM2: O = P.V + Q'.St ----
    float o[4][4];
#pragma unroll
    for (int di = 0; di < 4; ++di)
#pragma unroll
        for (int ei = 0; ei < 4; ++ei) o[di][ei] = 0.0f;

#pragma unroll 8
    for (int j = 0; j < NCK; ++j) {
        float a0 = ps[(i0 + 0) * NCK + j];
        float a1 = ps[(i0 + 1) * NCK + j];
        float a2 = ps[(i0 + 2) * NCK + j];
        float a3 = ps[(i0 + 3) * NCK + j];
        float4 bv = *(const float4*)(vs + j * PST + j0);
        o[0][0] += a0 * bv.x; o[0][1] += a0 * bv.y; o[0][2] += a0 * bv.z; o[0][3] += a0 * bv.w;
        o[1][0] += a1 * bv.x; o[1][1] += a1 * bv.y; o[1][2] += a1 * bv.z; o[1][3] += a1 * bv.w;
        o[2][0] += a2 * bv.x; o[2][1] += a2 * bv.y; o[2][2] += a2 * bv.z; o[2][3] += a2 * bv.w;
        o[3][0] += a3 * bv.x; o[3][1] += a3 * bv.y; o[3][2] += a3 * bv.z; o[3][3] += a3 * bv.w;
    }
#pragma unroll 8
    for (int d = 0; d < ND; ++d) {
        float a0 = qs[(i0 + 0) * PST + d];
        float a1 = qs[(i0 + 1) * PST + d];
        float a2 = qs[(i0 + 2) * PST + d];
        float a3 = qs[(i0 + 3) * PST + d];
        float4 bv = *(const float4*)(sts + d * PST + j0);
        o[0][0] += a0 * bv.x; o[0][1] += a0 * bv.y; o[0][2] += a0 * bv.z; o[0][3] += a0 * bv.w;
        o[1][0] += a1 * bv.x; o[1][1] += a1 * bv.y; o[1][2] += a1 * bv.z; o[1][3] += a1 * bv.w;
        o[2][0] += a2 * bv.x; o[2][1] += a2 * bv.y; o[2][2] += a2 * bv.z; o[2][3] += a2 * bv.w;
        o[3][0] += a3 * bv.x; o[3][1] += a3 * bv.y; o[3][2] += a3 * bv.z; o[3][3] += a3 * bv.w;
    }

    float* og = out + ((size_t)(b * NS + c0)) * NHID + h * ND;
#pragma unroll
    for (int di = 0; di < 4; ++di) {
        float4 w = make_float4(o[di][0], o[di][1], o[di][2], o[di][3]);
        *(float4*)&og[(size_t)(i0 + di) * NHID + j0] = w;
    }
}

// ---------------------------------------------------------------------------
extern "C" void kernel_launch(void* const* d_in, const int* in_sizes, int n_in,
                              void* d_out, int out_size) {
    (void)in_sizes; (void)n_in; (void)out_size;
    const float* Q = (const float*)d_in[0];
    const float* K = (const float*)d_in[1];
    const float* V = (const float*)d_in[2];
    float* out = (float*)d_out;

    table_kernel<<<(NS * 32) / 256, 256>>>();

    dim3 grid(NNC, NH, NB);
    passA_kernel<<<grid, 256>>>(K, V);
    scan_kernel<<<NBH, 256>>>();

    size_t shm = (size_t)(3 * NCK * PST + NCK * NCK) * sizeof(float);   // 68608 B
    cudaFuncSetAttribute(passC_kernel, cudaFuncAttributeMaxDynamicSharedMemorySize, (int)shm);
    passC_kernel<<<grid, 256, shm>>>(Q, K, V, out);
}

// round 9
// speedup vs baseline: 1.9005x; 1.4392x over previous
#include <cuda_runtime.h>
#include <math.h>

// Problem constants
#define NB   2
#define NS   2048
#define NH   16
#define ND   64
#define NHID 1024
#define NCK  64      // chunk size
#define NNC  32      // chunks per sequence
#define NBH  32      // NB*NH
#define PST  68      // padded smem row stride (floats)

// Scratch (static device globals -- no allocation allowed)
__device__ float4 g_tab[NS * 32];              // xPos table: (cos*sc, sin*sc, cos/sc, sin/sc)
__device__ float  g_qr[NBH * NS * ND];         // rotated Q, [bh][s][d]
__device__ float  g_kr[NBH * NS * ND];         // rotated K, [bh][s][d]
__device__ float  g_A [NBH * NNC * ND * ND];   // per-chunk state contributions
__device__ float  g_St[NBH * NNC * ND * ND];   // prefix-scanned states (state BEFORE chunk c)

__device__ __forceinline__ double head_lg(int h) {
    const double L0 = -3.4657359027997265;   // log(1/32)
    const double L1 = -6.2383246250395075;   // log(1/512)
    double g = 1.0 - exp(L0 + (L1 - L0) * ((double)h / 15.0));
    return log(g);
}

// ---------------------------------------------------------------------------
// Kernel 0: xPos table. tab[s][i] = (cos*sc, sin*sc, cos/sc, sin/sc)
// 65536 threads -- transcendentals computed ONCE.
// ---------------------------------------------------------------------------
__global__ __launch_bounds__(256)
void table_kernel() {
    int idx = blockIdx.x * 256 + threadIdx.x;   // [0, 2048*32)
    int i = idx & 31;
    int s = idx >> 5;
    float invf = (float)(1.0 / pow(10000.0, (double)i / 32.0));
    float bs   = (2.0f * (float)i + 25.6f) / 89.6f;   // (2i + 0.4*64)/(1.4*64)
    float pos  = (float)s;
    float sn, cs;
    sincosf(pos * invf, &sn, &cs);
    float sc = powf(bs, pos * (1.0f / 512.0f));
    float iv = 1.0f / sc;
    g_tab[idx] = make_float4(cs * sc, sn * sc, cs * iv, sn * iv);
}

// ---------------------------------------------------------------------------
// Kernel 0.5: rope_lite -- rotation via table, zero transcendentals,
// fully coalesced. One thread per (bh, s, pair).
// ---------------------------------------------------------------------------
__global__ __launch_bounds__(256)
void rope_lite_kernel(const float* __restrict__ Q, const float* __restrict__ K) {
    int idx = blockIdx.x * 256 + threadIdx.x;  // [0, NBH*NS*32)
    int i  = idx & 31;
    int s  = (idx >> 5) & (NS - 1);
    int bh = idx >> 16;
    int h  = bh & (NH - 1);
    int b  = bh >> 4;

    float4 t = g_tab[(s << 5) + i];            // (cos*sc, sin*sc, cos/sc, sin/sc)

    int gin = (b * NS + s) * NHID + h * ND + 2 * i;
    float2 q = *(const float2*)(Q + gin);
    float2 k = *(const float2*)(K + gin);

    int gout = (bh * NS + s) * ND + 2 * i;
    float2 qo, ko;
    qo.x = q.x * t.x - q.y * t.y;
    qo.y = q.y * t.x + q.x * t.y;
    ko.x = k.x * t.z - k.y * t.w;
    ko.y = k.y * t.z + k.x * t.w;
    *(float2*)(g_qr + gout) = qo;
    *(float2*)(g_kr + gout) = ko;
}

// ---------------------------------------------------------------------------
// Kernel 1: A_c[d][e] = sum_j gamma^(C-j) k'[j][d] v[j][e]   (Round-6 proven)
// ---------------------------------------------------------------------------
__global__ __launch_bounds__(256)
void passA_kernel(const float* __restrict__ V) {
    __shared__ float ks[NCK * PST];
    __shared__ float vs[NCK * PST];
    __shared__ float wr[NCK];

    int c = blockIdx.x, h = blockIdx.y, b = blockIdx.z;
    int bh = b * NH + h;
    int tid = threadIdx.x;

    if (tid < NCK) {
        double lg = head_lg(h);
        wr[tid] = (float)exp(lg * (double)(NCK - tid));   // gamma^(C-j)
    }
    __syncthreads();

    int c0 = c * NCK;
    const float* kg = g_kr + (bh * NS + c0) * ND;
    const float* vg = V + (b * NS + c0) * NHID + h * ND;

#pragma unroll
    for (int t = 0; t < 16; ++t) {
        int idx = tid + t * 256;
        int r = idx >> 6, d = idx & 63;
        ks[r * PST + d] = kg[r * ND + d] * wr[r];
        vs[r * PST + d] = vg[r * NHID + d];
    }
    __syncthreads();

    int ty = tid >> 4, tx = tid & 15;
    float acc[4][4];
#pragma unroll
    for (int di = 0; di < 4; ++di)
#pragma unroll
        for (int ei = 0; ei < 4; ++ei) acc[di][ei] = 0.0f;

#pragma unroll 8
    for (int j = 0; j < NCK; ++j) {
        float a0 = ks[j * PST + 4 * ty + 0];
        float a1 = ks[j * PST + 4 * ty + 1];
        float a2 = ks[j * PST + 4 * ty + 2];
        float a3 = ks[j * PST + 4 * ty + 3];
        float4 bv = *(const float4*)(vs + j * PST + 4 * tx);
        acc[0][0] += a0 * bv.x; acc[0][1] += a0 * bv.y; acc[0][2] += a0 * bv.z; acc[0][3] += a0 * bv.w;
        acc[1][0] += a1 * bv.x; acc[1][1] += a1 * bv.y; acc[1][2] += a1 * bv.z; acc[1][3] += a1 * bv.w;
        acc[2][0] += a2 * bv.x; acc[2][1] += a2 * bv.y; acc[2][2] += a2 * bv.z; acc[2][3] += a2 * bv.w;
        acc[3][0] += a3 * bv.x; acc[3][1] += a3 * bv.y; acc[3][2] += a3 * bv.z; acc[3][3] += a3 * bv.w;
    }

    float* ag = g_A + ((size_t)bh * NNC + c) * ND * ND;
#pragma unroll
    for (int di = 0; di < 4; ++di) {
        float4 w = make_float4(acc[di][0], acc[di][1], acc[di][2], acc[di][3]);
        *(float4*)&ag[(4 * ty + di) * ND + 4 * tx] = w;
    }
}

// ---------------------------------------------------------------------------
// Kernel 2: prefix scan, 4x parallel: grid (NBH*4), quarter-plane per CTA,
// float4 per thread per step.
// ---------------------------------------------------------------------------
__global__ __launch_bounds__(256)
void scan_kernel() {
    int blk = blockIdx.x;
    int bh = blk >> 2;
    int qtr = blk & 3;
    int h = bh & (NH - 1);
    int tid = threadIdx.x;
    double lg = head_lg(h);
    float dec = (float)exp(lg * (double)NCK);

    float4 st = make_float4(0.f, 0.f, 0.f, 0.f);
    size_t base = (size_t)bh * NNC * ND * ND + qtr * 1024 + tid * 4;

    for (int c = 0; c < NNC; ++c) {
        size_t off = base + (size_t)c * ND * ND;
        *(float4*)(g_St + off) = st;
        float4 a = *(const float4*)(g_A + off);
        st.x = st.x * dec + a.x;
        st.y = st.y * dec + a.y;
        st.z = st.z * dec + a.z;
        st.w = st.w * dec + a.w;
    }
}

// ---------------------------------------------------------------------------
// Kernel 3: per-chunk output (Round-6 GEMM bodies).
// smem diet: ps overlays ksT; St staged over vs between GEMM2a and GEMM2b.
// smem = qs(4352) + ksT(4096) + vs(4352) + wq/wk(128) = 12928 fl = 50.5KB
//   -> 4 CTAs/SM.
// ---------------------------------------------------------------------------
extern __shared__ float smC[];

__global__ __launch_bounds__(256, 4)
void passC_kernel(const float* __restrict__ V, float* __restrict__ out) {
    float* qs  = smC;                            // [i][d]  NCK*PST
    float* ksT = smC + NCK * PST;                // [d][j] swizzled; reused as ps[i][j]
    float* vs  = smC + NCK * PST + NCK * NCK;    // [j][e]; reused as sts[d'][e]
    float* wq  = vs + NCK * PST;                 // [NCK] gamma^i
    float* wk  = wq + NCK;                       // [NCK] gamma^{-j}

    int c = blockIdx.x, h = blockIdx.y, b = blockIdx.z;
    int bh = b * NH + h;
    int tid = threadIdx.x;
    int c0 = c * NCK;

    if (tid < NCK) {
        double lg = head_lg(h);
        wq[tid] = (float)exp(lg * (double)tid);
        wk[tid] = (float)exp(-lg * (double)tid);
    }
    __syncthreads();

    const float* qg = g_qr + (bh * NS + c0) * ND;
    const float* kg = g_kr + (bh * NS + c0) * ND;
    const float* vg = V + (b * NS + c0) * NHID + h * ND;

#pragma unroll
    for (int t = 0; t < 16; ++t) {
        int idx = tid + t * 256;
        int r = idx >> 6, d = idx & 63;
        qs[r * PST + d] = qg[r * ND + d] * wq[r];
        float kv = kg[r * ND + d] * wk[r];
        ksT[d * NCK + (((r >> 2) ^ (d & 15)) << 2) + (r & 3)] = kv;
        vs[r * PST + d] = vg[r * NHID + d];
    }
    __syncthreads();

    int ty = tid >> 4, tx = tid & 15;
    int i0 = 4 * ty, j0 = 4 * tx;

    // ---- GEMM1: P = Q'.K'^T ----
    float acc[4][4];
#pragma unroll
    for (int di = 0; di < 4; ++di)
#pragma unroll
        for (int ei = 0; ei < 4; ++ei) acc[di][ei] = 0.0f;

#pragma unroll 8
    for (int d = 0; d < ND; ++d) {
        float a0 = qs[(i0 + 0) * PST + d];
        float a1 = qs[(i0 + 1) * PST + d];
        float a2 = qs[(i0 + 2) * PST + d];
        float a3 = qs[(i0 + 3) * PST + d];
        float4 bv = *(const float4*)&ksT[d * NCK + ((tx ^ (d & 15)) << 2)];
        acc[0][0] += a0 * bv.x; acc[0][1] += a0 * bv.y; acc[0][2] += a0 * bv.z; acc[0][3] += a0 * bv.w;
        acc[1][0] += a1 * bv.x; acc[1][1] += a1 * bv.y; acc[1][2] += a1 * bv.z; acc[1][3] += a1 * bv.w;
        acc[2][0] += a2 * bv.x; acc[2][1] += a2 * bv.y; acc[2][2] += a2 * bv.z; acc[2][3] += a2 * bv.w;
        acc[3][0] += a3 * bv.x; acc[3][1] += a3 * bv.y; acc[3][2] += a3 * bv.z; acc[3][3] += a3 * bv.w;
    }
    __syncthreads();   // done reading ksT

    // ---- mask + stage P into ksT's space ----
    float* ps = ksT;
#pragma unroll
    for (int di = 0; di < 4; ++di) {
        int ii = i0 + di;
        float4 w;
        w.x = (j0 + 0 <= ii) ? acc[di][0] : 0.0f;
        w.y = (j0 + 1 <= ii) ? acc[di][1] : 0.0f;
        w.z = (j0 + 2 <= ii) ? acc[di][2] : 0.0f;
        w.w = (j0 + 3 <= ii) ? acc[di][3] : 0.0f;
        *(float4*)&ps[ii * NCK + j0] = w;
    }
    __syncthreads();

    // ---- GEMM2a: O = P.V ----
    float o[4][4];
#pragma unroll
    for (int di = 0; di < 4; ++di)
#pragma unroll
        for (int ei = 0; ei < 4; ++ei) o[di][ei] = 0.0f;

#pragma unroll 8
    for (int j = 0; j < NCK; ++j) {
        float a0 = ps[(i0 + 0) * NCK + j];
        float a1 = ps[(i0 + 1) * NCK + j];
        float a2 = ps[(i0 + 2) * NCK + j];
        float a3 = ps[(i0 + 3) * NCK + j];
        float4 bv = *(const float4*)(vs + j * PST + j0);
        o[0][0] += a0 * bv.x; o[0][1] += a0 * bv.y; o[0][2] += a0 * bv.z; o[0][3] += a0 * bv.w;
        o[1][0] += a1 * bv.x; o[1][1] += a1 * bv.y; o[1][2] += a1 * bv.z; o[1][3] += a1 * bv.w;
        o[2][0] += a2 * bv.x; o[2][1] += a2 * bv.y; o[2][2] += a2 * bv.z; o[2][3] += a2 * bv.w;
        o[3][0] += a3 * bv.x; o[3][1] += a3 * bv.y; o[3][2] += a3 * bv.z; o[3][3] += a3 * bv.w;
    }
    __syncthreads();   // done reading vs

    // ---- stage St over vs ----
    {
        const float* stg = g_St + ((size_t)bh * NNC + c) * ND * ND;
#pragma unroll
        for (int t = 0; t < 16; ++t) {
            int idx = tid + t * 256;
            int r = idx >> 6, e = idx & 63;
            vs[r * PST + e] = stg[idx];
        }
    }
    __syncthreads();

    // ---- GEMM2b: O += Q'.St ----
    float* sts = vs;
#pragma unroll 8
    for (int d = 0; d < ND; ++d) {
        float a0 = qs[(i0 + 0) * PST + d];
        float a1 = qs[(i0 + 1) * PST + d];
        float a2 = qs[(i0 + 2) * PST + d];
        float a3 = qs[(i0 + 3) * PST + d];
        float4 bv = *(const float4*)(sts + d * PST + j0);
        o[0][0] += a0 * bv.x; o[0][1] += a0 * bv.y; o[0][2] += a0 * bv.z; o[0][3] += a0 * bv.w;
        o[1][0] += a1 * bv.x; o[1][1] += a1 * bv.y; o[1][2] += a1 * bv.z; o[1][3] += a1 * bv.w;
        o[2][0] += a2 * bv.x; o[2][1] += a2 * bv.y; o[2][2] += a2 * bv.z; o[2][3] += a2 * bv.w;
        o[3][0] += a3 * bv.x; o[3][1] += a3 * bv.y; o[3][2] += a3 * bv.z; o[3][3] += a3 * bv.w;
    }

    float* og = out + ((size_t)(b * NS + c0)) * NHID + h * ND;
#pragma unroll
    for (int di = 0; di < 4; ++di) {
        float4 w = make_float4(o[di][0], o[di][1], o[di][2], o[di][3]);
        *(float4*)&og[(size_t)(i0 + di) * NHID + j0] = w;
    }
}

// ---------------------------------------------------------------------------
extern "C" void kernel_launch(void* const* d_in, const int* in_sizes, int n_in,
                              void* d_out, int out_size) {
    (void)in_sizes; (void)n_in; (void)out_size;
    const float* Q = (const float*)d_in[0];
    const float* K = (const float*)d_in[1];
    const float* V = (const float*)d_in[2];
    float* out = (float*)d_out;

    table_kernel<<<(NS * 32) / 256, 256>>>();
    rope_lite_kernel<<<(NBH * NS * 32) / 256, 256>>>(Q, K);

    dim3 grid(NNC, NH, NB);
    passA_kernel<<<grid, 256>>>(V);
    scan_kernel<<<NBH * 4, 256>>>();

    size_t shm = (size_t)(2 * NCK * PST + NCK * NCK + 2 * NCK) * sizeof(float);  // 51712 B
    cudaFuncSetAttribute(passC_kernel, cudaFuncAttributeMaxDynamicSharedMemorySize, (int)shm);
    passC_kernel<<<grid, 256, shm>>>(V, out);
}

// round 10
// speedup vs baseline: 1.9881x; 1.0461x over previous
#include <cuda_runtime.h>
#include <math.h>

// Problem constants
#define NB   2
#define NS   2048
#define NH   16
#define ND   64
#define NHID 1024
#define NCK  64      // chunk size
#define NNC  32      // chunks per sequence
#define NBH  32      // NB*NH
#define PST  68      // padded smem row stride (floats)

// Scratch (static device globals -- no allocation allowed)
__device__ float4 g_tab[NS * 32];              // xPos table: (cos*sc, sin*sc, cos/sc, sin/sc)
__device__ float  g_qr[NBH * NS * ND];         // rotated Q, [bh][s][d]
__device__ float  g_kr[NBH * NS * ND];         // rotated K, [bh][s][d]
__device__ float  g_A [NBH * NNC * ND * ND];   // per-chunk state contributions
__device__ float  g_St[NBH * NNC * ND * ND];   // prefix-scanned states (state BEFORE chunk c)

__device__ __forceinline__ double head_lg(int h) {
    const double L0 = -3.4657359027997265;   // log(1/32)
    const double L1 = -6.2383246250395075;   // log(1/512)
    double g = 1.0 - exp(L0 + (L1 - L0) * ((double)h / 15.0));
    return log(g);
}

// ---------------------------------------------------------------------------
// Kernel 0: xPos table. tab[s][i] = (cos*sc, sin*sc, cos/sc, sin/sc)
// ---------------------------------------------------------------------------
__global__ __launch_bounds__(256)
void table_kernel() {
    int idx = blockIdx.x * 256 + threadIdx.x;   // [0, 2048*32)
    int i = idx & 31;
    int s = idx >> 5;
    float invf = (float)(1.0 / pow(10000.0, (double)i / 32.0));
    float bs   = (2.0f * (float)i + 25.6f) / 89.6f;   // (2i + 0.4*64)/(1.4*64)
    float pos  = (float)s;
    float sn, cs;
    sincosf(pos * invf, &sn, &cs);
    float sc = powf(bs, pos * (1.0f / 512.0f));
    float iv = 1.0f / sc;
    g_tab[idx] = make_float4(cs * sc, sn * sc, cs * iv, sn * iv);
}

// ---------------------------------------------------------------------------
// Kernel 0.5: rope_lite -- rotation via table, zero transcendentals, coalesced.
// ---------------------------------------------------------------------------
__global__ __launch_bounds__(256)
void rope_lite_kernel(const float* __restrict__ Q, const float* __restrict__ K) {
    int idx = blockIdx.x * 256 + threadIdx.x;  // [0, NBH*NS*32)
    int i  = idx & 31;
    int s  = (idx >> 5) & (NS - 1);
    int bh = idx >> 16;
    int h  = bh & (NH - 1);
    int b  = bh >> 4;

    float4 t = g_tab[(s << 5) + i];            // (cos*sc, sin*sc, cos/sc, sin/sc)

    int gin = (b * NS + s) * NHID + h * ND + 2 * i;
    float2 q = *(const float2*)(Q + gin);
    float2 k = *(const float2*)(K + gin);

    int gout = (bh * NS + s) * ND + 2 * i;
    float2 qo, ko;
    qo.x = q.x * t.x - q.y * t.y;
    qo.y = q.y * t.x + q.x * t.y;
    ko.x = k.x * t.z - k.y * t.w;
    ko.y = k.y * t.z + k.x * t.w;
    *(float2*)(g_qr + gout) = qo;
    *(float2*)(g_kr + gout) = ko;
}

// ---------------------------------------------------------------------------
// Kernel 1: A_c[d][e] = sum_j gamma^(C-j) k'[j][d] v[j][e]   (proven)
// ---------------------------------------------------------------------------
__global__ __launch_bounds__(256)
void passA_kernel(const float* __restrict__ V) {
    __shared__ float ks[NCK * PST];
    __shared__ float vs[NCK * PST];
    __shared__ float wr[NCK];

    int c = blockIdx.x, h = blockIdx.y, b = blockIdx.z;
    int bh = b * NH + h;
    int tid = threadIdx.x;

    if (tid < NCK) {
        double lg = head_lg(h);
        wr[tid] = (float)exp(lg * (double)(NCK - tid));   // gamma^(C-j)
    }
    __syncthreads();

    int c0 = c * NCK;
    const float* kg = g_kr + (bh * NS + c0) * ND;
    const float* vg = V + (b * NS + c0) * NHID + h * ND;

#pragma unroll
    for (int t = 0; t < 16; ++t) {
        int idx = tid + t * 256;
        int r = idx >> 6, d = idx & 63;
        ks[r * PST + d] = kg[r * ND + d] * wr[r];
        vs[r * PST + d] = vg[r * NHID + d];
    }
    __syncthreads();

    int ty = tid >> 4, tx = tid & 15;
    float acc[4][4];
#pragma unroll
    for (int di = 0; di < 4; ++di)
#pragma unroll
        for (int ei = 0; ei < 4; ++ei) acc[di][ei] = 0.0f;

#pragma unroll 8
    for (int j = 0; j < NCK; ++j) {
        float a0 = ks[j * PST + 4 * ty + 0];
        float a1 = ks[j * PST + 4 * ty + 1];
        float a2 = ks[j * PST + 4 * ty + 2];
        float a3 = ks[j * PST + 4 * ty + 3];
        float4 bv = *(const float4*)(vs + j * PST + 4 * tx);
        acc[0][0] += a0 * bv.x; acc[0][1] += a0 * bv.y; acc[0][2] += a0 * bv.z; acc[0][3] += a0 * bv.w;
        acc[1][0] += a1 * bv.x; acc[1][1] += a1 * bv.y; acc[1][2] += a1 * bv.z; acc[1][3] += a1 * bv.w;
        acc[2][0] += a2 * bv.x; acc[2][1] += a2 * bv.y; acc[2][2] += a2 * bv.z; acc[2][3] += a2 * bv.w;
        acc[3][0] += a3 * bv.x; acc[3][1] += a3 * bv.y; acc[3][2] += a3 * bv.z; acc[3][3] += a3 * bv.w;
    }

    float* ag = g_A + ((size_t)bh * NNC + c) * ND * ND;
#pragma unroll
    for (int di = 0; di < 4; ++di) {
        float4 w = make_float4(acc[di][0], acc[di][1], acc[di][2], acc[di][3]);
        *(float4*)&ag[(4 * ty + di) * ND + 4 * tx] = w;
    }
}

// ---------------------------------------------------------------------------
// Kernel 2: prefix scan with depth-8 software pipeline (MLP=8).
// St_{c+1} = gamma^C * St_c + A_c.  The A-loads are independent of the
// running state, so 8 are kept in flight; the dep chain is just 32 FMAs.
// ---------------------------------------------------------------------------
__global__ __launch_bounds__(256)
void scan_kernel() {
    int blk = blockIdx.x;          // NBH*4
    int bh = blk >> 2;
    int qtr = blk & 3;
    int h = bh & (NH - 1);
    int tid = threadIdx.x;
    double lg = head_lg(h);
    float dec = (float)exp(lg * (double)NCK);

    size_t base = (size_t)bh * NNC * ND * ND + qtr * 1024 + tid * 4;

    float4 buf[8];
#pragma unroll
    for (int p = 0; p < 8; ++p)
        buf[p] = *(const float4*)(g_A + base + (size_t)p * ND * ND);

    float4 st = make_float4(0.f, 0.f, 0.f, 0.f);
#pragma unroll
    for (int c = 0; c < NNC; ++c) {
        *(float4*)(g_St + base + (size_t)c * ND * ND) = st;
        float4 a = buf[c & 7];
        if (c + 8 < NNC)
            buf[c & 7] = *(const float4*)(g_A + base + (size_t)(c + 8) * ND * ND);
        st.x = st.x * dec + a.x;
        st.y = st.y * dec + a.y;
        st.z = st.z * dec + a.z;
        st.w = st.w * dec + a.w;
    }
}

// ---------------------------------------------------------------------------
// Kernel 3: per-chunk output (proven Round-9 version, 4 CTAs/SM).
// ---------------------------------------------------------------------------
extern __shared__ float smC[];

__global__ __launch_bounds__(256, 4)
void passC_kernel(const float* __restrict__ V, float* __restrict__ out) {
    float* qs  = smC;                            // [i][d]  NCK*PST
    float* ksT = smC + NCK * PST;                // [d][j] swizzled; reused as ps[i][j]
    float* vs  = smC + NCK * PST + NCK * NCK;    // [j][e]; reused as sts[d'][e]
    float* wq  = vs + NCK * PST;                 // [NCK] gamma^i
    float* wk  = wq + NCK;                       // [NCK] gamma^{-j}

    int c = blockIdx.x, h = blockIdx.y, b = blockIdx.z;
    int bh = b * NH + h;
    int tid = threadIdx.x;
    int c0 = c * NCK;

    if (tid < NCK) {
        double lg = head_lg(h);
        wq[tid] = (float)exp(lg * (double)tid);
        wk[tid] = (float)exp(-lg * (double)tid);
    }
    __syncthreads();

    const float* qg = g_qr + (bh * NS + c0) * ND;
    const float* kg = g_kr + (bh * NS + c0) * ND;
    const float* vg = V + (b * NS + c0) * NHID + h * ND;

#pragma unroll
    for (int t = 0; t < 16; ++t) {
        int idx = tid + t * 256;
        int r = idx >> 6, d = idx & 63;
        qs[r * PST + d] = qg[r * ND + d] * wq[r];
        float kv = kg[r * ND + d] * wk[r];
        ksT[d * NCK + (((r >> 2) ^ (d & 15)) << 2) + (r & 3)] = kv;
        vs[r * PST + d] = vg[r * NHID + d];
    }
    __syncthreads();

    int ty = tid >> 4, tx = tid & 15;
    int i0 = 4 * ty, j0 = 4 * tx;

    // ---- GEMM1: P = Q'.K'^T ----
    float acc[4][4];
#pragma unroll
    for (int di = 0; di < 4; ++di)
#pragma unroll
        for (int ei = 0; ei < 4; ++ei) acc[di][ei] = 0.0f;

#pragma unroll 8
    for (int d = 0; d < ND; ++d) {
        float a0 = qs[(i0 + 0) * PST + d];
        float a1 = qs[(i0 + 1) * PST + d];
        float a2 = qs[(i0 + 2) * PST + d];
        float a3 = qs[(i0 + 3) * PST + d];
        float4 bv = *(const float4*)&ksT[d * NCK + ((tx ^ (d & 15)) << 2)];
        acc[0][0] += a0 * bv.x; acc[0][1] += a0 * bv.y; acc[0][2] += a0 * bv.z; acc[0][3] += a0 * bv.w;
        acc[1][0] += a1 * bv.x; acc[1][1] += a1 * bv.y; acc[1][2] += a1 * bv.z; acc[1][3] += a1 * bv.w;
        acc[2][0] += a2 * bv.x; acc[2][1] += a2 * bv.y; acc[2][2] += a2 * bv.z; acc[2][3] += a2 * bv.w;
        acc[3][0] += a3 * bv.x; acc[3][1] += a3 * bv.y; acc[3][2] += a3 * bv.z; acc[3][3] += a3 * bv.w;
    }
    __syncthreads();   // done reading ksT

    // ---- mask + stage P into ksT's space ----
    float* ps = ksT;
#pragma unroll
    for (int di = 0; di < 4; ++di) {
        int ii = i0 + di;
        float4 w;
        w.x = (j0 + 0 <= ii) ? acc[di][0] : 0.0f;
        w.y = (j0 + 1 <= ii) ? acc[di][1] : 0.0f;
        w.z = (j0 + 2 <= ii) ? acc[di][2] : 0.0f;
        w.w = (j0 + 3 <= ii) ? acc[di][3] : 0.0f;
        *(float4*)&ps[ii * NCK + j0] = w;
    }
    __syncthreads();

    // ---- GEMM2a: O = P.V ----
    float o[4][4];
#pragma unroll
    for (int di = 0; di < 4; ++di)
#pragma unroll
        for (int ei = 0; ei < 4; ++ei) o[di][ei] = 0.0f;

#pragma unroll 8
    for (int j = 0; j < NCK; ++j) {
        float a0 = ps[(i0 + 0) * NCK + j];
        float a1 = ps[(i0 + 1) * NCK + j];
        float a2 = ps[(i0 + 2) * NCK + j];
        float a3 = ps[(i0 + 3) * NCK + j];
        float4 bv = *(const float4*)(vs + j * PST + j0);
        o[0][0] += a0 * bv.x; o[0][1] += a0 * bv.y; o[0][2] += a0 * bv.z; o[0][3] += a0 * bv.w;
        o[1][0] += a1 * bv.x; o[1][1] += a1 * bv.y; o[1][2] += a1 * bv.z; o[1][3] += a1 * bv.w;
        o[2][0] += a2 * bv.x; o[2][1] += a2 * bv.y; o[2][2] += a2 * bv.z; o[2][3] += a2 * bv.w;
        o[3][0] += a3 * bv.x; o[3][1] += a3 * bv.y; o[3][2] += a3 * bv.z; o[3][3] += a3 * bv.w;
    }
    __syncthreads();   // done reading vs

    // ---- stage St over vs ----
    {
        const float* stg = g_St + ((size_t)bh * NNC + c) * ND * ND;
#pragma unroll
        for (int t = 0; t < 16; ++t) {
            int idx = tid + t * 256;
            int r = idx >> 6, e = idx & 63;
            vs[r * PST + e] = stg[idx];
        }
    }
    __syncthreads();

    // ---- GEMM2b: O += Q'.St ----
    float* sts = vs;
#pragma unroll 8
    for (int d = 0; d < ND; ++d) {
        float a0 = qs[(i0 + 0) * PST + d];
        float a1 = qs[(i0 + 1) * PST + d];
        float a2 = qs[(i0 + 2) * PST + d];
        float a3 = qs[(i0 + 3) * PST + d];
        float4 bv = *(const float4*)(sts + d * PST + j0);
        o[0][0] += a0 * bv.x; o[0][1] += a0 * bv.y; o[0][2] += a0 * bv.z; o[0][3] += a0 * bv.w;
        o[1][0] += a1 * bv.x; o[1][1] += a1 * bv.y; o[1][2] += a1 * bv.z; o[1][3] += a1 * bv.w;
        o[2][0] += a2 * bv.x; o[2][1] += a2 * bv.y; o[2][2] += a2 * bv.z; o[2][3] += a2 * bv.w;
        o[3][0] += a3 * bv.x; o[3][1] += a3 * bv.y; o[3][2] += a3 * bv.z; o[3][3] += a3 * bv.w;
    }

    float* og = out + ((size_t)(b * NS + c0)) * NHID + h * ND;
#pragma unroll
    for (int di = 0; di < 4; ++di) {
        float4 w = make_float4(o[di][0], o[di][1], o[di][2], o[di][3]);
        *(float4*)&og[(size_t)(i0 + di) * NHID + j0] = w;
    }
}

// ---------------------------------------------------------------------------
extern "C" void kernel_launch(void* const* d_in, const int* in_sizes, int n_in,
                              void* d_out, int out_size) {
    (void)in_sizes; (void)n_in; (void)out_size;
    const float* Q = (const float*)d_in[0];
    const float* K = (const float*)d_in[1];
    const float* V = (const float*)d_in[2];
    float* out = (float*)d_out;

    table_kernel<<<(NS * 32) / 256, 256>>>();
    rope_lite_kernel<<<(NBH * NS * 32) / 256, 256>>>(Q, K);

    dim3 grid(NNC, NH, NB);
    passA_kernel<<<grid, 256>>>(V);
    scan_kernel<<<NBH * 4, 256>>>();

    size_t shm = (size_t)(2 * NCK * PST + NCK * NCK + 2 * NCK) * sizeof(float);  // 51712 B
    cudaFuncSetAttribute(passC_kernel, cudaFuncAttributeMaxDynamicSharedMemorySize, (int)shm);
    passC_kernel<<<grid, 256, shm>>>(V, out);
}